// round 1
// baseline (speedup 1.0000x reference)
#include <cuda_runtime.h>

// Tensor: (1024, 1024, 3, 3) fp32
#define OC_N    1024
#define IC_N    1024
#define KK_N    9
#define ROWS_N  (OC_N * IC_N)        // 1048576 kernel rows of 9
#define N_TOT   (ROWS_N * KK_N)      // 9437184
#define N_VEC4  (N_TOT / 4)          // 2359296

__device__ int                g_maxabs_bits;
__device__ float              g_scale;
__device__ float              g_rcp;
__device__ float              g_row_resid[ROWS_N];   // 4 MB
__device__ unsigned long long g_row_cand[ROWS_N];    // 8 MB

// ---------------------------------------------------------------------------
__global__ void k_init() { g_maxabs_bits = 0; }

// ---------------------------------------------------------------------------
// Pass A: global max|t| reduction. Positive floats order like their int bits.
__global__ void __launch_bounds__(256) k_maxabs(const float4* __restrict__ in) {
    float m = 0.0f;
    for (int i = blockIdx.x * blockDim.x + threadIdx.x; i < N_VEC4;
         i += gridDim.x * blockDim.x) {
        float4 v = in[i];
        m = fmaxf(m, fmaxf(fmaxf(fabsf(v.x), fabsf(v.y)),
                           fmaxf(fabsf(v.z), fabsf(v.w))));
    }
#pragma unroll
    for (int o = 16; o > 0; o >>= 1)
        m = fmaxf(m, __shfl_xor_sync(0xFFFFFFFFu, m, o));
    __shared__ float sm[8];
    if ((threadIdx.x & 31) == 0) sm[threadIdx.x >> 5] = m;
    __syncthreads();
    if (threadIdx.x < 8) {
        m = sm[threadIdx.x];
#pragma unroll
        for (int o = 4; o > 0; o >>= 1)
            m = fmaxf(m, __shfl_xor_sync(0xFFu, m, o));
        if (threadIdx.x == 0) atomicMax(&g_maxabs_bits, __float_as_int(m));
    }
}

// ---------------------------------------------------------------------------
// scale = max_abs / 127 (IEEE), plus correctly-rounded reciprocal for the
// shared-divisor Markstein division in k_rows.
__global__ void k_prep() {
    float ma = __int_as_float(g_maxabs_bits);
    float s  = __fdiv_rn(ma, 127.0f);
    g_scale  = s;
    g_rcp    = __frcp_rn(s);
}

// ---------------------------------------------------------------------------
// Pass B: per kernel-row (9 elems) SQuant stage.
//  - x = clip(t/scale, -127, 127); rn = rint(x); re = rn - x
//  - n_flip = rint(|sum re|); flip top-n_flip by priority |re| (stable)
//  - boundary (last flipped) -> candidate key for stage 2, opposite direction
// Writes rn*scale to out, residual + candidate key to side arrays.
__global__ void __launch_bounds__(256) k_rows(const float* __restrict__ in,
                                              float* __restrict__ out) {
    __shared__ __align__(16) float tile[256 * KK_N];  // 9216 B

    const float4* in4 = reinterpret_cast<const float4*>(in)
                        + (size_t)blockIdx.x * 576;
    float4* t4 = reinterpret_cast<float4*>(tile);
#pragma unroll
    for (int i = threadIdx.x; i < 576; i += 256) t4[i] = in4[i];
    __syncthreads();

    const float scl = g_scale;
    const float rcp = g_rcp;

    // gcd(9,32)=1 -> thread*9+i is bank-conflict-free across a warp.
    float rn[9], re[9], p[9];
    float esum = 0.0f;
#pragma unroll
    for (int i = 0; i < 9; i++) {
        float t  = tile[threadIdx.x * 9 + i];
        float q0 = __fmul_rn(t, rcp);                          // Markstein div:
        float x  = __fmaf_rn(__fmaf_rn(-scl, q0, t), rcp, q0); // == t/scl (RN)
        x = fminf(fmaxf(x, -127.0f), 127.0f);
        float r = rintf(x);           // round-half-to-even == jnp.round
        rn[i] = r;
        re[i] = __fadd_rn(r, -x);
        esum  = __fadd_rn(esum, re[i]);
    }

    const int   nf = (int)rintf(fabsf(esum));
    const bool  up = (esum < 0.0f);
    const float d1 = up ? 1.0f : -1.0f;
#pragma unroll
    for (int i = 0; i < 9; i++) {
        float c = up ? -re[i] : re[i];   // candidate iff re has right sign
        p[i] = (c > 0.0f) ? c : 0.0f;    // (|x|==127 => re==0 => prio 0 anyway)
    }

    const int row     = blockIdx.x * 256 + threadIdx.x;
    const int rowInOc = row & (IC_N - 1);

    float resid = 0.0f;
    unsigned long long cand = 0ull;
#pragma unroll
    for (int i = 0; i < 9; i++) {
        int rank = 0;
#pragma unroll
        for (int j = 0; j < 9; j++)   // stable (prio desc, index asc) rank
            rank += (int)((p[j] > p[i]) || ((p[j] == p[i]) && (j < i)));
        bool  fl  = (rank < nf);
        float re2 = fl ? __fadd_rn(re[i], d1) : re[i];
        resid = __fadd_rn(resid, re2);
        if (fl) {
            rn[i] += d1;
            if (rank == nf - 1) {   // boundary element
                int elemFlat = rowInOc * 9 + i;
                cand = ((unsigned long long)(up ? 1u : 0u) << 63)
                     | ((unsigned long long)__float_as_uint(fabsf(re2)) << 32)
                     | (unsigned long long)(unsigned)(9216 - elemFlat);
            }
        }
    }
    g_row_resid[row] = resid;
    g_row_cand[row]  = cand;

    __syncthreads();
#pragma unroll
    for (int i = 0; i < 9; i++)
        tile[threadIdx.x * 9 + i] = __fmul_rn(rn[i], scl);
    __syncthreads();

    float4* out4 = reinterpret_cast<float4*>(out) + (size_t)blockIdx.x * 576;
#pragma unroll
    for (int i = threadIdx.x; i < 576; i += 256) out4[i] = t4[i];
}

// ---------------------------------------------------------------------------
// Pass C: per-OC channel stage. Only stage-1 boundary elements have nonzero
// priority; flipping a boundary with the stored opposite direction reverts its
// stage-1 flip (un/dn == original rn) => out[elem] += +/- scale.
__global__ void __launch_bounds__(128) k_channel(float* __restrict__ out) {
    __shared__ unsigned long long skeys[1024];
    __shared__ float sred[128];

    const int oc   = blockIdx.x;
    const int t    = threadIdx.x;
    const int base = oc << 10;

    float s = 0.0f;
#pragma unroll
    for (int i = t; i < 1024; i += 128) {
        s += g_row_resid[base + i];
        skeys[i] = g_row_cand[base + i];
    }
    sred[t] = s;
    __syncthreads();
#pragma unroll
    for (int o = 64; o > 0; o >>= 1) {
        if (t < o) sred[t] += sred[t + o];
        __syncthreads();
    }
    const float esum = sred[0];
    const int   nf   = (int)rintf(fabsf(esum));
    if (nf == 0) return;
    const bool upc = (esum < 0.0f);

    if (t < 32) {
        // stage-2 up flips boundaries of stage-1 DOWN-flipped rows (dir bit 0)
        const unsigned long long want = upc ? 0ull : 1ull;
        const float delta = upc ? g_scale : -g_scale;
        for (int it = 0; it < nf; it++) {
            unsigned long long m = 0ull;
#pragma unroll 4
            for (int j = 0; j < 32; j++) {   // lane-strided: conflict-free LDS.64
                unsigned long long k = skeys[j * 32 + t];
                if ((k >> 63) == want && k != 0ull) {
                    unsigned long long c = k & 0x7FFFFFFFFFFFFFFFull;
                    if (c > m) m = c;
                }
            }
#pragma unroll
            for (int o = 16; o > 0; o >>= 1) {
                unsigned long long v = __shfl_xor_sync(0xFFFFFFFFu, m, o);
                if (v > m) m = v;
            }
            if (m == 0ull) break;   // fewer candidates than n_flip (safe clamp)
            const int elemFlat = 9216 - (int)(unsigned)(m & 0xFFFFFFFFull);
            if (t == 0) {
                out[(size_t)oc * 9216 + elemFlat] += delta;
                skeys[elemFlat / 9] = 0ull;   // row's single candidate consumed
            }
            __syncwarp();
        }
    }
}

// ---------------------------------------------------------------------------
extern "C" void kernel_launch(void* const* d_in, const int* in_sizes, int n_in,
                              void* d_out, int out_size) {
    const float* in  = (const float*)d_in[0];
    float*       out = (float*)d_out;

    k_init<<<1, 1>>>();
    k_maxabs<<<1184, 256>>>((const float4*)in);
    k_prep<<<1, 1>>>();
    k_rows<<<ROWS_N / 256, 256>>>(in, out);
    k_channel<<<OC_N, 128>>>(out);
}

// round 2
// speedup vs baseline: 1.3410x; 1.3410x over previous
#include <cuda_runtime.h>

// Tensor: (1024, 1024, 3, 3) fp32
#define OC_N    1024
#define IC_N    1024
#define ROWS_N  (OC_N * IC_N)        // 1048576 kernel rows of 9
#define N_TOT   (ROWS_N * 9)         // 9437184
#define N_VEC4  (N_TOT / 4)          // 2359296
#define MAX_GRID 1152                // 1152*256 threads * 8 float4 = N_VEC4 exactly

__device__ float              g_part_max[MAX_GRID];
__device__ float              g_scale;
__device__ float              g_rcp;
__device__ float              g_part_resid[ROWS_N / 256]; // 4096 block partials
__device__ unsigned long long g_row_cand[ROWS_N];         // 8 MB (L2-resident)

// ---------------------------------------------------------------------------
// Pass A: per-block max|t| partials (no atomics, no init kernel needed).
__global__ void __launch_bounds__(256) k_maxabs(const float4* __restrict__ in) {
    const int base = blockIdx.x * 256 + threadIdx.x;
    const int stride = MAX_GRID * 256;
    float m = 0.0f;
#pragma unroll
    for (int k = 0; k < 8; k++) {
        float4 v = in[base + k * stride];
        m = fmaxf(m, fmaxf(fmaxf(fabsf(v.x), fabsf(v.y)),
                           fmaxf(fabsf(v.z), fabsf(v.w))));
    }
#pragma unroll
    for (int o = 16; o > 0; o >>= 1)
        m = fmaxf(m, __shfl_xor_sync(0xFFFFFFFFu, m, o));
    __shared__ float sm[8];
    if ((threadIdx.x & 31) == 0) sm[threadIdx.x >> 5] = m;
    __syncthreads();
    if (threadIdx.x == 0) {
        m = sm[0];
#pragma unroll
        for (int i = 1; i < 8; i++) m = fmaxf(m, sm[i]);
        g_part_max[blockIdx.x] = m;
    }
}

// ---------------------------------------------------------------------------
// Final max reduce + scale = max/127 (IEEE) + correctly-rounded reciprocal.
__global__ void __launch_bounds__(128) k_prep() {
    float m = 0.0f;
    for (int i = threadIdx.x; i < MAX_GRID; i += 128)
        m = fmaxf(m, g_part_max[i]);
#pragma unroll
    for (int o = 16; o > 0; o >>= 1)
        m = fmaxf(m, __shfl_xor_sync(0xFFFFFFFFu, m, o));
    __shared__ float sm[4];
    if ((threadIdx.x & 31) == 0) sm[threadIdx.x >> 5] = m;
    __syncthreads();
    if (threadIdx.x == 0) {
        m = fmaxf(fmaxf(sm[0], sm[1]), fmaxf(sm[2], sm[3]));
        float s = __fdiv_rn(m, 127.0f);
        g_scale  = s;
        g_rcp    = __frcp_rn(s);
    }
}

// ---------------------------------------------------------------------------
// Pass B: per kernel-row (9 elems) SQuant stage.
__global__ void __launch_bounds__(256) k_rows(const float* __restrict__ in,
                                              float* __restrict__ out) {
    __shared__ __align__(16) float tile[2304];  // 9216 B
    __shared__ float swred[8];

    const float4* in4 = reinterpret_cast<const float4*>(in)
                        + (size_t)blockIdx.x * 576;
    float4* t4 = reinterpret_cast<float4*>(tile);
#pragma unroll
    for (int i = threadIdx.x; i < 576; i += 256) t4[i] = in4[i];
    __syncthreads();

    const float scl = g_scale;
    const float rcp = g_rcp;

    // gcd(9,32)=1 -> thread*9+i is bank-conflict-free across a warp.
    float rn[9], re[9], p[9];
    float esum = 0.0f;
#pragma unroll
    for (int i = 0; i < 9; i++) {
        float t  = tile[threadIdx.x * 9 + i];
        float q0 = __fmul_rn(t, rcp);                          // Markstein div:
        float x  = __fmaf_rn(__fmaf_rn(-scl, q0, t), rcp, q0); // == t/scl (RN)
        x = fminf(fmaxf(x, -127.0f), 127.0f);
        float r = rintf(x);           // round-half-to-even == jnp.round
        rn[i] = r;
        re[i] = __fadd_rn(r, -x);
        esum  = __fadd_rn(esum, re[i]);
    }

    const int   nf = (int)rintf(fabsf(esum));
    const bool  up = (esum < 0.0f);
    const float d1 = up ? 1.0f : -1.0f;
#pragma unroll
    for (int i = 0; i < 9; i++) {
        float c = up ? -re[i] : re[i];   // candidate iff re has right sign
        p[i] = fmaxf(c, 0.0f);
    }

    // Pairwise stable rank: tie (==) -> lower index outranks.
    int rank[9];
#pragma unroll
    for (int j = 0; j < 9; j++) rank[j] = j;
#pragma unroll
    for (int i = 0; i < 8; i++)
#pragma unroll
        for (int j = i + 1; j < 9; j++) {
            int g = (int)(p[j] > p[i]);
            rank[i] += g;
            rank[j] -= g;
        }

    // Flips: exactly nf flipped (nf <= #candidates holds in stage 1).
    int bi = -1;
#pragma unroll
    for (int i = 0; i < 9; i++) {
        if (rank[i] < nf)      rn[i] += d1;
        if (rank[i] == nf - 1) bi = i;          // boundary element
        tile[threadIdx.x * 9 + i] = rn[i];      // own slots only: no hazard
    }
    float resid = __fmaf_rn((float)nf, d1, esum);

    unsigned long long cand = 0ull;
    const int row = blockIdx.x * 256 + threadIdx.x;
    if (bi >= 0) {
        float re2 = __fadd_rn(re[bi], d1);
        int elemFlat = (row & (IC_N - 1)) * 9 + bi;
        cand = ((unsigned long long)(up ? 1u : 0u) << 63)
             | ((unsigned long long)__float_as_uint(fabsf(re2)) << 32)
             | (unsigned long long)(unsigned)(9216 - elemFlat);
    }
    g_row_cand[row] = cand;

    // block-reduce residual -> one partial per 256 rows
#pragma unroll
    for (int o = 16; o > 0; o >>= 1)
        resid += __shfl_xor_sync(0xFFFFFFFFu, resid, o);
    if ((threadIdx.x & 31) == 0) swred[threadIdx.x >> 5] = resid;
    __syncthreads();
    if (threadIdx.x == 0) {
        float s = swred[0];
#pragma unroll
        for (int i = 1; i < 8; i++) s += swred[i];
        g_part_resid[blockIdx.x] = s;
    }

    float4* out4 = reinterpret_cast<float4*>(out) + (size_t)blockIdx.x * 576;
#pragma unroll
    for (int i = threadIdx.x; i < 576; i += 256) {
        float4 v = t4[i];
        v.x = __fmul_rn(v.x, scl); v.y = __fmul_rn(v.y, scl);
        v.z = __fmul_rn(v.z, scl); v.w = __fmul_rn(v.w, scl);
        out4[i] = v;
    }
}

// ---------------------------------------------------------------------------
// Pass C: per-OC channel stage = top-nf selection over <=1024 candidate keys
// (each row holds at most one candidate, so picks are independent).
// Tournament: 32 group-maxima; per pick: shfl-max over 32 + rescan one group.
__global__ void __launch_bounds__(256) k_channel(float* __restrict__ out) {
    __shared__ unsigned long long skeys[1024];
    __shared__ unsigned long long gmax[32];
    __shared__ float s_esum;

    const int oc   = blockIdx.x;
    const int tid  = threadIdx.x;
    const int w    = tid >> 5;
    const int lane = tid & 31;

    if (tid == 0) {
        const int pb = oc << 2;
        s_esum = ((g_part_resid[pb] + g_part_resid[pb + 1])
                + g_part_resid[pb + 2]) + g_part_resid[pb + 3];
    }
    __syncthreads();

    const float esum = s_esum;
    const int   nf   = (int)rintf(fabsf(esum));
    if (nf == 0) return;
    const bool  upc  = (esum < 0.0f);
    // stage-2 up-flip reverts a stage-1 DOWN-flipped boundary (dir bit 0)
    const unsigned long long want = upc ? 0ull : 1ull;

    const size_t base = (size_t)oc << 10;
#pragma unroll
    for (int s = 0; s < 4; s++) {
        const int g = (w << 2) | s;                  // group of 32 rows
        unsigned long long k = g_row_cand[base + g * 32 + lane];
        unsigned long long m =
            (k != 0ull && (k >> 63) == want) ? (k & 0x7FFFFFFFFFFFFFFFull)
                                             : 0ull;
        skeys[g * 32 + lane] = m;
#pragma unroll
        for (int o = 16; o > 0; o >>= 1) {
            unsigned long long v = __shfl_xor_sync(0xFFFFFFFFu, m, o);
            if (v > m) m = v;
        }
        if (lane == 0) gmax[g] = m;
    }
    __syncthreads();

    if (w == 0) {
        const float delta = upc ? g_scale : -g_scale;
        for (int it = 0; it < nf; it++) {
            unsigned long long m = gmax[lane];
#pragma unroll
            for (int o = 16; o > 0; o >>= 1) {
                unsigned long long v = __shfl_xor_sync(0xFFFFFFFFu, m, o);
                if (v > m) m = v;
            }
            if (m == 0ull) break;   // candidates exhausted (safe clamp)
            const int elemFlat = 9216 - (int)(unsigned)(m & 0xFFFFFFFFull);
            const int rowSel   = elemFlat / 9;
            const int g        = rowSel >> 5;
            if (lane == 0) {
                out[(size_t)oc * 9216 + elemFlat] += delta;
                skeys[rowSel] = 0ull;     // consume this row's candidate
            }
            __syncwarp();
            unsigned long long m2 = skeys[g * 32 + lane];
#pragma unroll
            for (int o = 16; o > 0; o >>= 1) {
                unsigned long long v = __shfl_xor_sync(0xFFFFFFFFu, m2, o);
                if (v > m2) m2 = v;
            }
            if (lane == 0) gmax[g] = m2;
            __syncwarp();
        }
    }
}

// ---------------------------------------------------------------------------
extern "C" void kernel_launch(void* const* d_in, const int* in_sizes, int n_in,
                              void* d_out, int out_size) {
    const float* in  = (const float*)d_in[0];
    float*       out = (float*)d_out;

    k_maxabs<<<MAX_GRID, 256>>>((const float4*)in);
    k_prep<<<1, 128>>>();
    k_rows<<<ROWS_N / 256, 256>>>(in, out);
    k_channel<<<OC_N, 256>>>(out);
}